// round 12
// baseline (speedup 1.0000x reference)
#include <cuda_runtime.h>
#include <cuda_bf16.h>
#include <cuda_fp16.h>
#include <cstdint>

// ---------------- problem constants ----------------
#define BSZ   16
#define ALEN 1024
#define PLEN 2048
#define LDIM 768

// ================= scratch (device globals) =================
__device__ __align__(256) float g_W [(size_t)BSZ * PLEN * ALEN];

// bf16 triple-K operand buffers (logit chain only)
__device__ __align__(256) __nv_bfloat16 g_A3 [(size_t)16384 * 2304];
__device__ __align__(256) __nv_bfloat16 g_P3 [(size_t)32768 * 2304];
__device__ __align__(256) __nv_bfloat16 g_Ag3[(size_t)16384 * 2304];
__device__ __align__(256) __nv_bfloat16 g_Gw3[(size_t)2304 * 768];   // [Kp,N] for B-trans

// fp16 single operand buffers (post-softmax chain) — all row-major
__device__ __align__(256) __half g_Wh  [(size_t)32768 * 1024];
__device__ __align__(256) __half g_Ph  [(size_t)32768 * 768];
__device__ __align__(256) __half g_Agh [(size_t)16384 * 768];
__device__ __align__(256) __half g_U6h [(size_t)16384 * 1536];
__device__ __align__(256) __half g_U7h [(size_t)32768 * 1536];
__device__ __align__(256) __half g_Fah2[(size_t)1536 * 768];
__device__ __align__(256) __half g_Fph2[(size_t)1536 * 768];

// ================= helpers =================
__device__ __forceinline__ uint32_t smem_u32(const void* p) {
    uint32_t a;
    asm("{ .reg .u64 t; cvta.to.shared.u64 t, %1; cvt.u32.u64 %0, t; }" : "=r"(a) : "l"(p));
    return a;
}

#define LDSM4(r0, r1, r2, r3, a)                                              \
    asm volatile("ldmatrix.sync.aligned.m8n8.x4.shared.b16 {%0,%1,%2,%3}, [%4];" \
                 : "=r"(r0), "=r"(r1), "=r"(r2), "=r"(r3) : "r"(a))
#define LDSM4T(r0, r1, r2, r3, a)                                             \
    asm volatile("ldmatrix.sync.aligned.m8n8.x4.trans.shared.b16 {%0,%1,%2,%3}, [%4];" \
                 : "=r"(r0), "=r"(r1), "=r"(r2), "=r"(r3) : "r"(a))

__device__ __forceinline__ void mma_bf16(float* c, uint32_t a0, uint32_t a1, uint32_t a2,
                                         uint32_t a3, uint32_t b0, uint32_t b1) {
    asm volatile("mma.sync.aligned.m16n8k16.row.col.f32.bf16.bf16.f32 "
                 "{%0,%1,%2,%3}, {%4,%5,%6,%7}, {%8,%9}, {%0,%1,%2,%3};"
                 : "+f"(c[0]), "+f"(c[1]), "+f"(c[2]), "+f"(c[3])
                 : "r"(a0), "r"(a1), "r"(a2), "r"(a3), "r"(b0), "r"(b1));
}
__device__ __forceinline__ void mma_fp16(float* c, uint32_t a0, uint32_t a1, uint32_t a2,
                                         uint32_t a3, uint32_t b0, uint32_t b1) {
    asm volatile("mma.sync.aligned.m16n8k16.row.col.f32.f16.f16.f32 "
                 "{%0,%1,%2,%3}, {%4,%5,%6,%7}, {%8,%9}, {%0,%1,%2,%3};"
                 : "+f"(c[0]), "+f"(c[1]), "+f"(c[2]), "+f"(c[3])
                 : "r"(a0), "r"(a1), "r"(a2), "r"(a3), "r"(b0), "r"(b1));
}

// ================= tensor-core GEMM (mma.sync) =================
// C[M,N](f32) = opA(A) * opB(B)^T-style, 16-bit operands.
// 128x128 block tile, 128 threads (2x2 warps, 64x64 warp tile),
// K-chunk 64, 3-stage cp.async pipeline, 2 CTAs/SM, fragment double-buffer.
// TA/TB: operand stored [Kp, M/N] row-major, consumed via ldmatrix.trans.
// EPI: 0 fp32 C | 1 +bias | 2 relu(+bias)
//      3 combo: fp16 out2[r,c]=C-aux, out2[r,c+N]=C*aux (aux fp16, stride 2N)
//      4 Ag: bias add; bf16 triple out2 (hi,lo,hi; stride 3N) + fp16 out3
#define NSTRIDE 144
#define TSTRIDE 272
#define TILEB   18432
#define STAGEB  (2 * TILEB)
#define NSTAGE  3
#define SMEMSZ  (NSTAGE * STAGEB)   // 110592 B

__device__ __forceinline__ void ld_tile_n(uint32_t sdst, const char* g, int rowB, int tid) {
#pragma unroll
    for (int i = 0; i < 8; i++) {
        int idx = i * 128 + tid;
        int row = idx >> 3;
        int c = idx & 7;
        asm volatile("cp.async.cg.shared.global [%0], [%1], 16;\n"
                     :: "r"(sdst + row * NSTRIDE + c * 16),
                        "l"(g + (long long)row * rowB + c * 16));
    }
}
__device__ __forceinline__ void ld_tile_t(uint32_t sdst, const char* g, int rowB, int tid) {
#pragma unroll
    for (int i = 0; i < 8; i++) {
        int idx = i * 128 + tid;
        int row = idx >> 4;
        int c = idx & 15;
        asm volatile("cp.async.cg.shared.global [%0], [%1], 16;\n"
                     :: "r"(sdst + row * TSTRIDE + c * 16),
                        "l"(g + (long long)row * rowB + c * 16));
    }
}

template<int EPI, bool FP16, bool TA, bool TB>
__global__ __launch_bounds__(128, 2)
void tgemm(const uint16_t* __restrict__ Aop,
           const uint16_t* __restrict__ Bop,
           const float* __restrict__ bias,
           const __half* __restrict__ aux,
           float* __restrict__ Cout,
           void* __restrict__ out2,
           void* __restrict__ out3,
           int N, int Kp, int ldA, int ldB,
           long long bsA, long long bsB, long long bsC)
{
    extern __shared__ __align__(128) char smem[];
    const uint32_t sbase = smem_u32(smem);
    const int tid  = threadIdx.x;
    const int wid  = tid >> 5;
    const int lane = tid & 31;
    const int wm = wid & 1;
    const int wn = wid >> 1;

    const int rowBA = ldA * 2;
    const int rowBB = ldB * 2;
    const char* Abase = ((const char*)Aop) + 2LL * (bsA * blockIdx.z +
                        (TA ? (long long)blockIdx.y * 128
                            : (long long)blockIdx.y * 128 * ldA));
    const char* Bbase = ((const char*)Bop) + 2LL * (bsB * blockIdx.z +
                        (TB ? (long long)blockIdx.x * 128
                            : (long long)blockIdx.x * 128 * ldB));

    const int ntiles = Kp >> 6;

    float c[4][8][4];
#pragma unroll
    for (int i = 0; i < 4; i++)
#pragma unroll
        for (int j = 0; j < 8; j++) {
            c[i][j][0] = 0.f; c[i][j][1] = 0.f; c[i][j][2] = 0.f; c[i][j][3] = 0.f;
        }

    auto a_chunk = [&](int k) -> const char* {
        return TA ? Abase + (long long)k * 64 * rowBA : Abase + k * 128;
    };
    auto b_chunk = [&](int k) -> const char* {
        return TB ? Bbase + (long long)k * 64 * rowBB : Bbase + k * 128;
    };

#pragma unroll
    for (int s = 0; s < 2; s++) {
        if (TA) ld_tile_t(sbase + s * STAGEB,         a_chunk(s), rowBA, tid);
        else    ld_tile_n(sbase + s * STAGEB,         a_chunk(s), rowBA, tid);
        if (TB) ld_tile_t(sbase + s * STAGEB + TILEB, b_chunk(s), rowBB, tid);
        else    ld_tile_n(sbase + s * STAGEB + TILEB, b_chunk(s), rowBB, tid);
        asm volatile("cp.async.commit_group;\n" ::: "memory");
    }

    const uint32_t aoff = TA
        ? (uint32_t)(((lane & 7) + ((lane >> 4) << 3)) * TSTRIDE + (((lane >> 3) & 1) << 4)
                     + wm * 128)
        : (uint32_t)((wm * 64 + (lane & 15)) * NSTRIDE + ((lane >> 4) << 4));
    const uint32_t boff = TB
        ? (uint32_t)((lane & 15) * TSTRIDE + ((lane >> 4) << 4) + wn * 128)
        : (uint32_t)((wn * 64 + ((lane >> 4) << 3) + (lane & 7)) * NSTRIDE
                     + (((lane >> 3) & 1) << 4));

    uint32_t afb[2][16], bfb[2][16];

    for (int ks = 0; ks < ntiles; ks++) {
        const int b = ks % NSTAGE;
        asm volatile("cp.async.wait_group 1;\n" ::: "memory");
        __syncthreads();

        const uint32_t sA = sbase + b * STAGEB;
        const uint32_t sB = sA + TILEB;

#pragma unroll
        for (int bi = 0; bi < 4; bi++) {
            if (TB) LDSM4T(bfb[0][bi*4+0], bfb[0][bi*4+1], bfb[0][bi*4+2], bfb[0][bi*4+3],
                           sB + boff + bi * 32);
            else    LDSM4 (bfb[0][bi*4+0], bfb[0][bi*4+1], bfb[0][bi*4+2], bfb[0][bi*4+3],
                           sB + boff + bi * 16 * NSTRIDE);
        }
#pragma unroll
        for (int mt = 0; mt < 4; mt++) {
            if (TA) LDSM4T(afb[0][mt*4+0], afb[0][mt*4+1], afb[0][mt*4+2], afb[0][mt*4+3],
                           sA + aoff + mt * 32);
            else    LDSM4 (afb[0][mt*4+0], afb[0][mt*4+1], afb[0][mt*4+2], afb[0][mt*4+3],
                           sA + aoff + mt * 16 * NSTRIDE);
        }

#pragma unroll
        for (int kk = 0; kk < 4; kk++) {
            const int cur = kk & 1;
            const int nxt = cur ^ 1;
            if (kk < 3) {
#pragma unroll
                for (int bi = 0; bi < 4; bi++) {
                    if (TB) LDSM4T(bfb[nxt][bi*4+0], bfb[nxt][bi*4+1], bfb[nxt][bi*4+2], bfb[nxt][bi*4+3],
                                   sB + boff + (kk + 1) * 16 * TSTRIDE + bi * 32);
                    else    LDSM4 (bfb[nxt][bi*4+0], bfb[nxt][bi*4+1], bfb[nxt][bi*4+2], bfb[nxt][bi*4+3],
                                   sB + boff + bi * 16 * NSTRIDE + (kk + 1) * 32);
                }
#pragma unroll
                for (int mt = 0; mt < 4; mt++) {
                    if (TA) LDSM4T(afb[nxt][mt*4+0], afb[nxt][mt*4+1], afb[nxt][mt*4+2], afb[nxt][mt*4+3],
                                   sA + aoff + (kk + 1) * 16 * TSTRIDE + mt * 32);
                    else    LDSM4 (afb[nxt][mt*4+0], afb[nxt][mt*4+1], afb[nxt][mt*4+2], afb[nxt][mt*4+3],
                                   sA + aoff + mt * 16 * NSTRIDE + (kk + 1) * 32);
                }
            }
#pragma unroll
            for (int mt = 0; mt < 4; mt++) {
#pragma unroll
                for (int bi = 0; bi < 4; bi++) {
                    if (FP16) {
                        mma_fp16(c[mt][2*bi],   afb[cur][mt*4+0], afb[cur][mt*4+1],
                                 afb[cur][mt*4+2], afb[cur][mt*4+3],
                                 bfb[cur][bi*4+0], bfb[cur][bi*4+1]);
                        mma_fp16(c[mt][2*bi+1], afb[cur][mt*4+0], afb[cur][mt*4+1],
                                 afb[cur][mt*4+2], afb[cur][mt*4+3],
                                 bfb[cur][bi*4+2], bfb[cur][bi*4+3]);
                    } else {
                        mma_bf16(c[mt][2*bi],   afb[cur][mt*4+0], afb[cur][mt*4+1],
                                 afb[cur][mt*4+2], afb[cur][mt*4+3],
                                 bfb[cur][bi*4+0], bfb[cur][bi*4+1]);
                        mma_bf16(c[mt][2*bi+1], afb[cur][mt*4+0], afb[cur][mt*4+1],
                                 afb[cur][mt*4+2], afb[cur][mt*4+3],
                                 bfb[cur][bi*4+2], bfb[cur][bi*4+3]);
                    }
                }
            }
        }

        const int kl = ks + 2;
        if (kl < ntiles) {
            const int bl = kl % NSTAGE;
            if (TA) ld_tile_t(sbase + bl * STAGEB,         a_chunk(kl), rowBA, tid);
            else    ld_tile_n(sbase + bl * STAGEB,         a_chunk(kl), rowBA, tid);
            if (TB) ld_tile_t(sbase + bl * STAGEB + TILEB, b_chunk(kl), rowBB, tid);
            else    ld_tile_n(sbase + bl * STAGEB + TILEB, b_chunk(kl), rowBB, tid);
        }
        asm volatile("cp.async.commit_group;\n" ::: "memory");
    }

    // ---- epilogue ----
    const long long bz = blockIdx.z;
    const int row0 = blockIdx.y * 128 + wm * 64 + (lane >> 2);
    const int col0 = blockIdx.x * 128 + wn * 64 + (lane & 3) * 2;

#pragma unroll
    for (int mt = 0; mt < 4; mt++) {
#pragma unroll
        for (int nt = 0; nt < 8; nt++) {
            const int r = row0 + mt * 16;
            const int cl = col0 + nt * 8;
            float2 v0 = make_float2(c[mt][nt][0], c[mt][nt][1]);
            float2 v1 = make_float2(c[mt][nt][2], c[mt][nt][3]);

            if (EPI == 3) {
                const __half* Yb = aux + bsC * bz;
                __half* Ub = ((__half*)out2) + 2 * bsC * bz;
                const int ustr = 2 * N;
                float2 y0 = __half22float2(
                    *reinterpret_cast<const __half2*>(Yb + (long long)r * N + cl));
                float2 y1 = __half22float2(
                    *reinterpret_cast<const __half2*>(Yb + (long long)(r + 8) * N + cl));
                *reinterpret_cast<__half2*>(Ub + (long long)r * ustr + cl) =
                    __float22half2_rn(make_float2(v0.x - y0.x, v0.y - y0.y));
                *reinterpret_cast<__half2*>(Ub + (long long)r * ustr + cl + N) =
                    __float22half2_rn(make_float2(v0.x * y0.x, v0.y * y0.y));
                *reinterpret_cast<__half2*>(Ub + (long long)(r + 8) * ustr + cl) =
                    __float22half2_rn(make_float2(v1.x - y1.x, v1.y - y1.y));
                *reinterpret_cast<__half2*>(Ub + (long long)(r + 8) * ustr + cl + N) =
                    __float22half2_rn(make_float2(v1.x * y1.x, v1.y * y1.y));
                continue;
            }

            if (EPI == 1 || EPI == 2 || EPI == 4) {
                float2 bv = *reinterpret_cast<const float2*>(bias + cl);
                v0.x += bv.x; v0.y += bv.y; v1.x += bv.x; v1.y += bv.y;
            }
            if (EPI == 2) {
                v0.x = fmaxf(v0.x, 0.f); v0.y = fmaxf(v0.y, 0.f);
                v1.x = fmaxf(v1.x, 0.f); v1.y = fmaxf(v1.y, 0.f);
            }
            if (EPI <= 2) {
                float* Cb = Cout + bsC * bz;
                *reinterpret_cast<float2*>(Cb + (long long)r * N + cl)       = v0;
                *reinterpret_cast<float2*>(Cb + (long long)(r + 8) * N + cl) = v1;
            }

            if (EPI == 4) {
                __nv_bfloat16* T = (__nv_bfloat16*)out2;
                const int tstr = 3 * N;
                __nv_bfloat162 h0 = __float22bfloat162_rn(v0);
                __nv_bfloat162 h1 = __float22bfloat162_rn(v1);
                __nv_bfloat162 l0 = __float22bfloat162_rn(
                    make_float2(v0.x - __bfloat162float(h0.x), v0.y - __bfloat162float(h0.y)));
                __nv_bfloat162 l1 = __float22bfloat162_rn(
                    make_float2(v1.x - __bfloat162float(h1.x), v1.y - __bfloat162float(h1.y)));
                *reinterpret_cast<__nv_bfloat162*>(T + (long long)r * tstr + cl)          = h0;
                *reinterpret_cast<__nv_bfloat162*>(T + (long long)r * tstr + cl + N)      = l0;
                *reinterpret_cast<__nv_bfloat162*>(T + (long long)r * tstr + cl + 2 * N)  = h0;
                *reinterpret_cast<__nv_bfloat162*>(T + (long long)(r + 8) * tstr + cl)         = h1;
                *reinterpret_cast<__nv_bfloat162*>(T + (long long)(r + 8) * tstr + cl + N)     = l1;
                *reinterpret_cast<__nv_bfloat162*>(T + (long long)(r + 8) * tstr + cl + 2 * N) = h1;
                __half* Ah = (__half*)out3;
                *reinterpret_cast<__half2*>(Ah + (long long)r * N + cl)       = __float22half2_rn(v0);
                *reinterpret_cast<__half2*>(Ah + (long long)(r + 8) * N + cl) = __float22half2_rn(v1);
            }
        }
    }
}

// ================= conversion kernels (all pure streaming) =================
__global__ void split3_k(const float* __restrict__ in, __nv_bfloat16* __restrict__ out,
                         long long total2)
{
    long long i = (long long)blockIdx.x * blockDim.x + threadIdx.x;
    if (i >= total2) return;
    long long e = i * 2;
    long long r = e / 768;
    int c = (int)(e - r * 768);
    float2 v = *reinterpret_cast<const float2*>(in + e);
    __nv_bfloat162 h2 = __float22bfloat162_rn(v);
    __nv_bfloat162 l2 = __float22bfloat162_rn(
        make_float2(v.x - __bfloat162float(h2.x), v.y - __bfloat162float(h2.y)));
    __nv_bfloat16* o = out + r * 2304;
    *reinterpret_cast<__nv_bfloat162*>(o + c)        = h2;
    *reinterpret_cast<__nv_bfloat162*>(o + c + 768)  = h2;
    *reinterpret_cast<__nv_bfloat162*>(o + c + 1536) = l2;
}

__global__ void splitP_k(const float* __restrict__ in, __nv_bfloat16* __restrict__ P3,
                         __half* __restrict__ Ph, long long total2)
{
    long long i = (long long)blockIdx.x * blockDim.x + threadIdx.x;
    if (i >= total2) return;
    long long e = i * 2;
    long long r = e / 768;
    int c = (int)(e - r * 768);
    float2 v = *reinterpret_cast<const float2*>(in + e);
    __nv_bfloat162 h2 = __float22bfloat162_rn(v);
    __nv_bfloat162 l2 = __float22bfloat162_rn(
        make_float2(v.x - __bfloat162float(h2.x), v.y - __bfloat162float(h2.y)));
    __nv_bfloat16* o = P3 + r * 2304;
    *reinterpret_cast<__nv_bfloat162*>(o + c)        = h2;
    *reinterpret_cast<__nv_bfloat162*>(o + c + 768)  = h2;
    *reinterpret_cast<__nv_bfloat162*>(o + c + 1536) = l2;
    *reinterpret_cast<__half2*>(Ph + e) = __float22half2_rn(v);
}

__global__ void splitG_k(const float* __restrict__ in, __nv_bfloat16* __restrict__ out,
                         long long total2)
{
    long long i = (long long)blockIdx.x * blockDim.x + threadIdx.x;
    if (i >= total2) return;
    long long e = i * 2;
    float2 v = *reinterpret_cast<const float2*>(in + e);
    __nv_bfloat162 h2 = __float22bfloat162_rn(v);
    __nv_bfloat162 l2 = __float22bfloat162_rn(
        make_float2(v.x - __bfloat162float(h2.x), v.y - __bfloat162float(h2.y)));
    *reinterpret_cast<__nv_bfloat162*>(out + e)                   = h2;
    *reinterpret_cast<__nv_bfloat162*>(out + e + 768LL * 768)     = l2;
    *reinterpret_cast<__nv_bfloat162*>(out + e + 2LL * 768 * 768) = h2;
}

__global__ void cast_h(const float* __restrict__ in, __half* __restrict__ out, long long total2)
{
    long long i = (long long)blockIdx.x * blockDim.x + threadIdx.x;
    if (i >= total2) return;
    float2 v = *reinterpret_cast<const float2*>(in + i * 2);
    *reinterpret_cast<__half2*>(out + i * 2) = __float22half2_rn(v);
}

// ================= softmax over 1024 columns -> fp16 ==========
__global__ __launch_bounds__(256)
void softmax1024(const float* __restrict__ W, __half* __restrict__ Wh)
{
    const long long row = blockIdx.x;
    const float* w = W + row * 1024;
    const int t = threadIdx.x;
    float4 v = reinterpret_cast<const float4*>(w)[t];
    float m = fmaxf(fmaxf(v.x, v.y), fmaxf(v.z, v.w));
#pragma unroll
    for (int o = 16; o > 0; o >>= 1) m = fmaxf(m, __shfl_xor_sync(0xffffffffu, m, o));
    __shared__ float smax[8], ssum[8];
    if ((t & 31) == 0) smax[t >> 5] = m;
    __syncthreads();
    float bmax = smax[0];
#pragma unroll
    for (int i = 1; i < 8; i++) bmax = fmaxf(bmax, smax[i]);
    v.x = __expf(v.x - bmax); v.y = __expf(v.y - bmax);
    v.z = __expf(v.z - bmax); v.w = __expf(v.w - bmax);
    float s = v.x + v.y + v.z + v.w;
#pragma unroll
    for (int o = 16; o > 0; o >>= 1) s += __shfl_xor_sync(0xffffffffu, s, o);
    if ((t & 31) == 0) ssum[t >> 5] = s;
    __syncthreads();
    float tot = 0.f;
#pragma unroll
    for (int i = 0; i < 8; i++) tot += ssum[i];
    const float inv = 1.f / tot;
    __half* wh = Wh + row * 1024 + t * 4;
    *reinterpret_cast<__half2*>(wh)     = __float22half2_rn(make_float2(v.x * inv, v.y * inv));
    *reinterpret_cast<__half2*>(wh + 2) = __float22half2_rn(make_float2(v.z * inv, v.w * inv));
}

// ================= stream/event setup (static init, pre-checkpoint) ========
#define NGRP 4
static cudaStream_t s2;
static cudaEvent_t ev_fork1, ev_join1, ev_g[NGRP], ev_sm, ev_mp, ev_join2;
static struct StreamInit {
    StreamInit() {
        cudaStreamCreateWithFlags(&s2, cudaStreamNonBlocking);
        cudaEventCreateWithFlags(&ev_fork1, cudaEventDisableTiming);
        cudaEventCreateWithFlags(&ev_join1, cudaEventDisableTiming);
        for (int g = 0; g < NGRP; g++)
            cudaEventCreateWithFlags(&ev_g[g], cudaEventDisableTiming);
        cudaEventCreateWithFlags(&ev_sm, cudaEventDisableTiming);
        cudaEventCreateWithFlags(&ev_mp, cudaEventDisableTiming);
        cudaEventCreateWithFlags(&ev_join2, cudaEventDisableTiming);
    }
} s_streamInit;

// ================= launch =================
static inline int blk2(long long total2) { return (int)((total2 + 255) / 256); }

extern "C" void kernel_launch(void* const* d_in, const int* in_sizes, int n_in,
                              void* d_out, int out_size)
{
    (void)in_sizes; (void)n_in; (void)out_size;
    const float* A     = (const float*)d_in[0];
    const float* P     = (const float*)d_in[1];
    const float* G_w   = (const float*)d_in[2];
    const float* G_b   = (const float*)d_in[3];
    const float* fca_w = (const float*)d_in[4];
    const float* fca_b = (const float*)d_in[5];
    const float* fcp_w = (const float*)d_in[6];
    const float* fcp_b = (const float*)d_in[7];
    float* out = (float*)d_out;

    float *W;
    cudaGetSymbolAddress((void**)&W,  g_W);
    __nv_bfloat16 *A3, *P3, *Ag3, *Gw3;
    cudaGetSymbolAddress((void**)&A3,  g_A3);
    cudaGetSymbolAddress((void**)&P3,  g_P3);
    cudaGetSymbolAddress((void**)&Ag3, g_Ag3);
    cudaGetSymbolAddress((void**)&Gw3, g_Gw3);
    __half *Wh, *Ph, *Agh, *U6h, *U7h, *Fah2, *Fph2;
    cudaGetSymbolAddress((void**)&Wh,   g_Wh);
    cudaGetSymbolAddress((void**)&Ph,   g_Ph);
    cudaGetSymbolAddress((void**)&Agh,  g_Agh);
    cudaGetSymbolAddress((void**)&U6h,  g_U6h);
    cudaGetSymbolAddress((void**)&U7h,  g_U7h);
    cudaGetSymbolAddress((void**)&Fah2, g_Fah2);
    cudaGetSymbolAddress((void**)&Fph2, g_Fph2);

    cudaFuncSetAttribute((const void*)tgemm<4,false,false,true>,  cudaFuncAttributeMaxDynamicSharedMemorySize, SMEMSZ);
    cudaFuncSetAttribute((const void*)tgemm<0,false,false,false>, cudaFuncAttributeMaxDynamicSharedMemorySize, SMEMSZ);
    cudaFuncSetAttribute((const void*)tgemm<3,true,false,true>,   cudaFuncAttributeMaxDynamicSharedMemorySize, SMEMSZ);
    cudaFuncSetAttribute((const void*)tgemm<3,true,true,true>,    cudaFuncAttributeMaxDynamicSharedMemorySize, SMEMSZ);
    cudaFuncSetAttribute((const void*)tgemm<2,true,false,true>,   cudaFuncAttributeMaxDynamicSharedMemorySize, SMEMSZ);

    // ---- fork 1: P/weight conversions on s2; A/G conversions + GEMM1 on main ----
    cudaEventRecord(ev_fork1, 0);
    cudaStreamWaitEvent(s2, ev_fork1, 0);

    splitP_k<<<blk2(32768LL*768/2), 256, 0, s2>>>(P, P3, Ph, 32768LL*768/2);
    cast_h<<<blk2(1536LL*768/2), 256, 0, s2>>>(fca_w, Fah2, 1536LL*768/2);
    cast_h<<<blk2(1536LL*768/2), 256, 0, s2>>>(fcp_w, Fph2, 1536LL*768/2);
    cudaEventRecord(ev_join1, s2);

    split3_k<<<blk2(16384LL*768/2), 256>>>(A, A3, 16384LL*768/2);
    splitG_k<<<blk2(768LL*768/2),   256>>>(G_w, Gw3, 768LL*768/2);

    // 1) Ag = A @ G_w + G_b  (bf16 triple-K; B-trans) -> Ag3 + Agh
    tgemm<4,false,false,true><<<dim3(6, 128, 1), 128, SMEMSZ>>>(
        (const uint16_t*)A3, (const uint16_t*)Gw3, G_b, nullptr, nullptr, Ag3, Agh,
        768, 2304, 2304, 768, 0, 0, 0);

    cudaStreamWaitEvent(0, ev_join1, 0);

    // 2+3) GEMM2 grouped by batch on main; softmax per group pipelined on s2
    const int GB = BSZ / NGRP;   // 4 batches per group
    for (int g = 0; g < NGRP; g++) {
        const long long z0 = (long long)g * GB;
        tgemm<0,false,false,false><<<dim3(8, 16, GB), 128, SMEMSZ>>>(
            (const uint16_t*)(P3 + z0 * 2048LL * 2304),
            (const uint16_t*)(Ag3 + z0 * 1024LL * 2304),
            nullptr, nullptr, W + z0 * 2048LL * 1024, nullptr, nullptr,
            1024, 2304, 2304, 2304, 2048LL*2304, 1024LL*2304, 2048LL*1024);
        cudaEventRecord(ev_g[g], 0);
        cudaStreamWaitEvent(s2, ev_g[g], 0);
        softmax1024<<<GB * PLEN, 256, 0, s2>>>(
            W + z0 * 2048LL * 1024, Wh + z0 * 2048LL * 1024);
    }
    cudaEventRecord(ev_sm, s2);

    // ---- tails: s2 runs MA -> SA -> SP_part2; main runs MP -> SP_part1 ----
    // 5) MA = W^T @ P (fp16; A-trans Wh, B-trans Ph), combo with Agh -> U6h (s2)
    tgemm<3,true,true,true><<<dim3(6, 8, 16), 128, SMEMSZ, s2>>>(
        (const uint16_t*)Wh, (const uint16_t*)Ph, nullptr, Agh, nullptr, U6h, nullptr,
        768, 2048, 1024, 768, 2048LL*1024, 2048LL*768, 1024LL*768);
    // 6) SA = relu(U6 @ fca_w + fca_b)  (s2)
    tgemm<2,true,false,true><<<dim3(6, 128, 1), 128, SMEMSZ, s2>>>(
        (const uint16_t*)U6h, (const uint16_t*)Fah2, fca_b, nullptr, out, nullptr, nullptr,
        768, 1536, 1536, 768, 0, 0, 0);

    // 4) MP = W @ Ag (fp16; B-trans Agh), combo with Ph -> U7h (main, after softmax)
    cudaStreamWaitEvent(0, ev_sm, 0);
    tgemm<3,true,false,true><<<dim3(6, 16, 16), 128, SMEMSZ>>>(
        (const uint16_t*)Wh, (const uint16_t*)Agh, nullptr, Ph, nullptr, U7h, nullptr,
        768, 1024, 1024, 768, 2048LL*1024, 1024LL*768, 2048LL*768);
    cudaEventRecord(ev_mp, 0);

    // 7a) SP rows [0, 24576) on main (192 of 256 M-tiles)
    tgemm<2,true,false,true><<<dim3(6, 192, 1), 128, SMEMSZ>>>(
        (const uint16_t*)U7h, (const uint16_t*)Fph2, fcp_b, nullptr,
        out + 16384LL * 768, nullptr, nullptr,
        768, 1536, 1536, 768, 0, 0, 0);

    // 7b) SP rows [24576, 32768) on s2 (64 M-tiles), after SA and MP
    cudaStreamWaitEvent(s2, ev_mp, 0);
    tgemm<2,true,false,true><<<dim3(6, 64, 1), 128, SMEMSZ, s2>>>(
        (const uint16_t*)(U7h + 24576LL * 1536), (const uint16_t*)Fph2, fcp_b, nullptr,
        out + 16384LL * 768 + 24576LL * 768, nullptr, nullptr,
        768, 1536, 1536, 768, 0, 0, 0);
    cudaEventRecord(ev_join2, s2);

    cudaStreamWaitEvent(0, ev_join2, 0);
}

// round 13
// speedup vs baseline: 1.0249x; 1.0249x over previous
#include <cuda_runtime.h>
#include <cuda_bf16.h>
#include <cuda_fp16.h>
#include <cstdint>

// ---------------- problem constants ----------------
#define BSZ   16
#define ALEN 1024
#define PLEN 2048
#define LDIM 768

// ================= scratch (device globals) =================
__device__ __align__(256) float g_W [(size_t)BSZ * PLEN * ALEN];

// bf16 triple-K operand buffers (logit chain only)
__device__ __align__(256) __nv_bfloat16 g_A3 [(size_t)16384 * 2304];
__device__ __align__(256) __nv_bfloat16 g_P3 [(size_t)32768 * 2304];
__device__ __align__(256) __nv_bfloat16 g_Ag3[(size_t)16384 * 2304];
__device__ __align__(256) __nv_bfloat16 g_Gw3[(size_t)2304 * 768];   // [Kp,N] for B-trans

// fp16 single operand buffers (post-softmax chain) — all row-major
__device__ __align__(256) __half g_Wh  [(size_t)32768 * 1024];
__device__ __align__(256) __half g_Ph  [(size_t)32768 * 768];
__device__ __align__(256) __half g_Agh [(size_t)16384 * 768];
__device__ __align__(256) __half g_U6h [(size_t)16384 * 1536];
__device__ __align__(256) __half g_U7h [(size_t)32768 * 1536];
__device__ __align__(256) __half g_Fah2[(size_t)1536 * 768];
__device__ __align__(256) __half g_Fph2[(size_t)1536 * 768];

// ================= helpers =================
__device__ __forceinline__ uint32_t smem_u32(const void* p) {
    uint32_t a;
    asm("{ .reg .u64 t; cvta.to.shared.u64 t, %1; cvt.u32.u64 %0, t; }" : "=r"(a) : "l"(p));
    return a;
}

#define LDSM4(r0, r1, r2, r3, a)                                              \
    asm volatile("ldmatrix.sync.aligned.m8n8.x4.shared.b16 {%0,%1,%2,%3}, [%4];" \
                 : "=r"(r0), "=r"(r1), "=r"(r2), "=r"(r3) : "r"(a))
#define LDSM4T(r0, r1, r2, r3, a)                                             \
    asm volatile("ldmatrix.sync.aligned.m8n8.x4.trans.shared.b16 {%0,%1,%2,%3}, [%4];" \
                 : "=r"(r0), "=r"(r1), "=r"(r2), "=r"(r3) : "r"(a))

__device__ __forceinline__ void mma_bf16(float* c, uint32_t a0, uint32_t a1, uint32_t a2,
                                         uint32_t a3, uint32_t b0, uint32_t b1) {
    asm volatile("mma.sync.aligned.m16n8k16.row.col.f32.bf16.bf16.f32 "
                 "{%0,%1,%2,%3}, {%4,%5,%6,%7}, {%8,%9}, {%0,%1,%2,%3};"
                 : "+f"(c[0]), "+f"(c[1]), "+f"(c[2]), "+f"(c[3])
                 : "r"(a0), "r"(a1), "r"(a2), "r"(a3), "r"(b0), "r"(b1));
}
__device__ __forceinline__ void mma_fp16(float* c, uint32_t a0, uint32_t a1, uint32_t a2,
                                         uint32_t a3, uint32_t b0, uint32_t b1) {
    asm volatile("mma.sync.aligned.m16n8k16.row.col.f32.f16.f16.f32 "
                 "{%0,%1,%2,%3}, {%4,%5,%6,%7}, {%8,%9}, {%0,%1,%2,%3};"
                 : "+f"(c[0]), "+f"(c[1]), "+f"(c[2]), "+f"(c[3])
                 : "r"(a0), "r"(a1), "r"(a2), "r"(a3), "r"(b0), "r"(b1));
}

// ================= tensor-core GEMM (mma.sync) =================
// C[M,N](f32) = opA(A) * opB(B)^T-style, 16-bit operands.
// 128x128 block tile, 128 threads (2x2 warps, 64x64 warp tile),
// K-chunk 64, 3-stage cp.async pipeline, 2 CTAs/SM, fragment double-buffer.
// TA/TB: operand stored [Kp, M/N] row-major, consumed via ldmatrix.trans.
// EPI: 0 fp32 C | 1 +bias | 2 relu(+bias)
//      3 combo: fp16 out2[r,c]=C-aux, out2[r,c+N]=C*aux (aux fp16, stride 2N)
//      4 Ag: bias add; bf16 triple out2 (hi,lo,hi; stride 3N) + fp16 out3
#define NSTRIDE 144
#define TSTRIDE 272
#define TILEB   18432
#define STAGEB  (2 * TILEB)
#define NSTAGE  3
#define SMEMSZ  (NSTAGE * STAGEB)   // 110592 B

__device__ __forceinline__ void ld_tile_n(uint32_t sdst, const char* g, int rowB, int tid) {
#pragma unroll
    for (int i = 0; i < 8; i++) {
        int idx = i * 128 + tid;
        int row = idx >> 3;
        int c = idx & 7;
        asm volatile("cp.async.cg.shared.global [%0], [%1], 16;\n"
                     :: "r"(sdst + row * NSTRIDE + c * 16),
                        "l"(g + (long long)row * rowB + c * 16));
    }
}
__device__ __forceinline__ void ld_tile_t(uint32_t sdst, const char* g, int rowB, int tid) {
#pragma unroll
    for (int i = 0; i < 8; i++) {
        int idx = i * 128 + tid;
        int row = idx >> 4;
        int c = idx & 15;
        asm volatile("cp.async.cg.shared.global [%0], [%1], 16;\n"
                     :: "r"(sdst + row * TSTRIDE + c * 16),
                        "l"(g + (long long)row * rowB + c * 16));
    }
}

template<int EPI, bool FP16, bool TA, bool TB>
__global__ __launch_bounds__(128, 2)
void tgemm(const uint16_t* __restrict__ Aop,
           const uint16_t* __restrict__ Bop,
           const float* __restrict__ bias,
           const __half* __restrict__ aux,
           float* __restrict__ Cout,
           void* __restrict__ out2,
           void* __restrict__ out3,
           int N, int Kp, int ldA, int ldB,
           long long bsA, long long bsB, long long bsC)
{
    extern __shared__ __align__(128) char smem[];
    const uint32_t sbase = smem_u32(smem);
    const int tid  = threadIdx.x;
    const int wid  = tid >> 5;
    const int lane = tid & 31;
    const int wm = wid & 1;
    const int wn = wid >> 1;

    const int rowBA = ldA * 2;
    const int rowBB = ldB * 2;
    const char* Abase = ((const char*)Aop) + 2LL * (bsA * blockIdx.z +
                        (TA ? (long long)blockIdx.y * 128
                            : (long long)blockIdx.y * 128 * ldA));
    const char* Bbase = ((const char*)Bop) + 2LL * (bsB * blockIdx.z +
                        (TB ? (long long)blockIdx.x * 128
                            : (long long)blockIdx.x * 128 * ldB));

    const int ntiles = Kp >> 6;

    float c[4][8][4];
#pragma unroll
    for (int i = 0; i < 4; i++)
#pragma unroll
        for (int j = 0; j < 8; j++) {
            c[i][j][0] = 0.f; c[i][j][1] = 0.f; c[i][j][2] = 0.f; c[i][j][3] = 0.f;
        }

    auto a_chunk = [&](int k) -> const char* {
        return TA ? Abase + (long long)k * 64 * rowBA : Abase + k * 128;
    };
    auto b_chunk = [&](int k) -> const char* {
        return TB ? Bbase + (long long)k * 64 * rowBB : Bbase + k * 128;
    };

#pragma unroll
    for (int s = 0; s < 2; s++) {
        if (TA) ld_tile_t(sbase + s * STAGEB,         a_chunk(s), rowBA, tid);
        else    ld_tile_n(sbase + s * STAGEB,         a_chunk(s), rowBA, tid);
        if (TB) ld_tile_t(sbase + s * STAGEB + TILEB, b_chunk(s), rowBB, tid);
        else    ld_tile_n(sbase + s * STAGEB + TILEB, b_chunk(s), rowBB, tid);
        asm volatile("cp.async.commit_group;\n" ::: "memory");
    }

    const uint32_t aoff = TA
        ? (uint32_t)(((lane & 7) + ((lane >> 4) << 3)) * TSTRIDE + (((lane >> 3) & 1) << 4)
                     + wm * 128)
        : (uint32_t)((wm * 64 + (lane & 15)) * NSTRIDE + ((lane >> 4) << 4));
    const uint32_t boff = TB
        ? (uint32_t)((lane & 15) * TSTRIDE + ((lane >> 4) << 4) + wn * 128)
        : (uint32_t)((wn * 64 + ((lane >> 4) << 3) + (lane & 7)) * NSTRIDE
                     + (((lane >> 3) & 1) << 4));

    uint32_t afb[2][16], bfb[2][16];

    for (int ks = 0; ks < ntiles; ks++) {
        const int b = ks % NSTAGE;
        asm volatile("cp.async.wait_group 1;\n" ::: "memory");
        __syncthreads();

        const uint32_t sA = sbase + b * STAGEB;
        const uint32_t sB = sA + TILEB;

#pragma unroll
        for (int bi = 0; bi < 4; bi++) {
            if (TB) LDSM4T(bfb[0][bi*4+0], bfb[0][bi*4+1], bfb[0][bi*4+2], bfb[0][bi*4+3],
                           sB + boff + bi * 32);
            else    LDSM4 (bfb[0][bi*4+0], bfb[0][bi*4+1], bfb[0][bi*4+2], bfb[0][bi*4+3],
                           sB + boff + bi * 16 * NSTRIDE);
        }
#pragma unroll
        for (int mt = 0; mt < 4; mt++) {
            if (TA) LDSM4T(afb[0][mt*4+0], afb[0][mt*4+1], afb[0][mt*4+2], afb[0][mt*4+3],
                           sA + aoff + mt * 32);
            else    LDSM4 (afb[0][mt*4+0], afb[0][mt*4+1], afb[0][mt*4+2], afb[0][mt*4+3],
                           sA + aoff + mt * 16 * NSTRIDE);
        }

#pragma unroll
        for (int kk = 0; kk < 4; kk++) {
            const int cur = kk & 1;
            const int nxt = cur ^ 1;
            if (kk < 3) {
#pragma unroll
                for (int bi = 0; bi < 4; bi++) {
                    if (TB) LDSM4T(bfb[nxt][bi*4+0], bfb[nxt][bi*4+1], bfb[nxt][bi*4+2], bfb[nxt][bi*4+3],
                                   sB + boff + (kk + 1) * 16 * TSTRIDE + bi * 32);
                    else    LDSM4 (bfb[nxt][bi*4+0], bfb[nxt][bi*4+1], bfb[nxt][bi*4+2], bfb[nxt][bi*4+3],
                                   sB + boff + bi * 16 * NSTRIDE + (kk + 1) * 32);
                }
#pragma unroll
                for (int mt = 0; mt < 4; mt++) {
                    if (TA) LDSM4T(afb[nxt][mt*4+0], afb[nxt][mt*4+1], afb[nxt][mt*4+2], afb[nxt][mt*4+3],
                                   sA + aoff + (kk + 1) * 16 * TSTRIDE + mt * 32);
                    else    LDSM4 (afb[nxt][mt*4+0], afb[nxt][mt*4+1], afb[nxt][mt*4+2], afb[nxt][mt*4+3],
                                   sA + aoff + mt * 16 * NSTRIDE + (kk + 1) * 32);
                }
            }
#pragma unroll
            for (int mt = 0; mt < 4; mt++) {
#pragma unroll
                for (int bi = 0; bi < 4; bi++) {
                    if (FP16) {
                        mma_fp16(c[mt][2*bi],   afb[cur][mt*4+0], afb[cur][mt*4+1],
                                 afb[cur][mt*4+2], afb[cur][mt*4+3],
                                 bfb[cur][bi*4+0], bfb[cur][bi*4+1]);
                        mma_fp16(c[mt][2*bi+1], afb[cur][mt*4+0], afb[cur][mt*4+1],
                                 afb[cur][mt*4+2], afb[cur][mt*4+3],
                                 bfb[cur][bi*4+2], bfb[cur][bi*4+3]);
                    } else {
                        mma_bf16(c[mt][2*bi],   afb[cur][mt*4+0], afb[cur][mt*4+1],
                                 afb[cur][mt*4+2], afb[cur][mt*4+3],
                                 bfb[cur][bi*4+0], bfb[cur][bi*4+1]);
                        mma_bf16(c[mt][2*bi+1], afb[cur][mt*4+0], afb[cur][mt*4+1],
                                 afb[cur][mt*4+2], afb[cur][mt*4+3],
                                 bfb[cur][bi*4+2], bfb[cur][bi*4+3]);
                    }
                }
            }
        }

        const int kl = ks + 2;
        if (kl < ntiles) {
            const int bl = kl % NSTAGE;
            if (TA) ld_tile_t(sbase + bl * STAGEB,         a_chunk(kl), rowBA, tid);
            else    ld_tile_n(sbase + bl * STAGEB,         a_chunk(kl), rowBA, tid);
            if (TB) ld_tile_t(sbase + bl * STAGEB + TILEB, b_chunk(kl), rowBB, tid);
            else    ld_tile_n(sbase + bl * STAGEB + TILEB, b_chunk(kl), rowBB, tid);
        }
        asm volatile("cp.async.commit_group;\n" ::: "memory");
    }

    // ---- epilogue ----
    const long long bz = blockIdx.z;
    const int row0 = blockIdx.y * 128 + wm * 64 + (lane >> 2);
    const int col0 = blockIdx.x * 128 + wn * 64 + (lane & 3) * 2;

#pragma unroll
    for (int mt = 0; mt < 4; mt++) {
#pragma unroll
        for (int nt = 0; nt < 8; nt++) {
            const int r = row0 + mt * 16;
            const int cl = col0 + nt * 8;
            float2 v0 = make_float2(c[mt][nt][0], c[mt][nt][1]);
            float2 v1 = make_float2(c[mt][nt][2], c[mt][nt][3]);

            if (EPI == 3) {
                const __half* Yb = aux + bsC * bz;
                __half* Ub = ((__half*)out2) + 2 * bsC * bz;
                const int ustr = 2 * N;
                float2 y0 = __half22float2(
                    *reinterpret_cast<const __half2*>(Yb + (long long)r * N + cl));
                float2 y1 = __half22float2(
                    *reinterpret_cast<const __half2*>(Yb + (long long)(r + 8) * N + cl));
                *reinterpret_cast<__half2*>(Ub + (long long)r * ustr + cl) =
                    __float22half2_rn(make_float2(v0.x - y0.x, v0.y - y0.y));
                *reinterpret_cast<__half2*>(Ub + (long long)r * ustr + cl + N) =
                    __float22half2_rn(make_float2(v0.x * y0.x, v0.y * y0.y));
                *reinterpret_cast<__half2*>(Ub + (long long)(r + 8) * ustr + cl) =
                    __float22half2_rn(make_float2(v1.x - y1.x, v1.y - y1.y));
                *reinterpret_cast<__half2*>(Ub + (long long)(r + 8) * ustr + cl + N) =
                    __float22half2_rn(make_float2(v1.x * y1.x, v1.y * y1.y));
                continue;
            }

            if (EPI == 1 || EPI == 2 || EPI == 4) {
                float2 bv = *reinterpret_cast<const float2*>(bias + cl);
                v0.x += bv.x; v0.y += bv.y; v1.x += bv.x; v1.y += bv.y;
            }
            if (EPI == 2) {
                v0.x = fmaxf(v0.x, 0.f); v0.y = fmaxf(v0.y, 0.f);
                v1.x = fmaxf(v1.x, 0.f); v1.y = fmaxf(v1.y, 0.f);
            }
            if (EPI <= 2) {
                float* Cb = Cout + bsC * bz;
                *reinterpret_cast<float2*>(Cb + (long long)r * N + cl)       = v0;
                *reinterpret_cast<float2*>(Cb + (long long)(r + 8) * N + cl) = v1;
            }

            if (EPI == 4) {
                __nv_bfloat16* T = (__nv_bfloat16*)out2;
                const int tstr = 3 * N;
                __nv_bfloat162 h0 = __float22bfloat162_rn(v0);
                __nv_bfloat162 h1 = __float22bfloat162_rn(v1);
                __nv_bfloat162 l0 = __float22bfloat162_rn(
                    make_float2(v0.x - __bfloat162float(h0.x), v0.y - __bfloat162float(h0.y)));
                __nv_bfloat162 l1 = __float22bfloat162_rn(
                    make_float2(v1.x - __bfloat162float(h1.x), v1.y - __bfloat162float(h1.y)));
                *reinterpret_cast<__nv_bfloat162*>(T + (long long)r * tstr + cl)          = h0;
                *reinterpret_cast<__nv_bfloat162*>(T + (long long)r * tstr + cl + N)      = l0;
                *reinterpret_cast<__nv_bfloat162*>(T + (long long)r * tstr + cl + 2 * N)  = h0;
                *reinterpret_cast<__nv_bfloat162*>(T + (long long)(r + 8) * tstr + cl)         = h1;
                *reinterpret_cast<__nv_bfloat162*>(T + (long long)(r + 8) * tstr + cl + N)     = l1;
                *reinterpret_cast<__nv_bfloat162*>(T + (long long)(r + 8) * tstr + cl + 2 * N) = h1;
                __half* Ah = (__half*)out3;
                *reinterpret_cast<__half2*>(Ah + (long long)r * N + cl)       = __float22half2_rn(v0);
                *reinterpret_cast<__half2*>(Ah + (long long)(r + 8) * N + cl) = __float22half2_rn(v1);
            }
        }
    }
}

// ================= conversion kernels (all pure streaming) =================
__global__ void split3_k(const float* __restrict__ in, __nv_bfloat16* __restrict__ out,
                         long long total2)
{
    long long i = (long long)blockIdx.x * blockDim.x + threadIdx.x;
    if (i >= total2) return;
    long long e = i * 2;
    long long r = e / 768;
    int c = (int)(e - r * 768);
    float2 v = *reinterpret_cast<const float2*>(in + e);
    __nv_bfloat162 h2 = __float22bfloat162_rn(v);
    __nv_bfloat162 l2 = __float22bfloat162_rn(
        make_float2(v.x - __bfloat162float(h2.x), v.y - __bfloat162float(h2.y)));
    __nv_bfloat16* o = out + r * 2304;
    *reinterpret_cast<__nv_bfloat162*>(o + c)        = h2;
    *reinterpret_cast<__nv_bfloat162*>(o + c + 768)  = h2;
    *reinterpret_cast<__nv_bfloat162*>(o + c + 1536) = l2;
}

__global__ void splitP_k(const float* __restrict__ in, __nv_bfloat16* __restrict__ P3,
                         __half* __restrict__ Ph, long long total2)
{
    long long i = (long long)blockIdx.x * blockDim.x + threadIdx.x;
    if (i >= total2) return;
    long long e = i * 2;
    long long r = e / 768;
    int c = (int)(e - r * 768);
    float2 v = *reinterpret_cast<const float2*>(in + e);
    __nv_bfloat162 h2 = __float22bfloat162_rn(v);
    __nv_bfloat162 l2 = __float22bfloat162_rn(
        make_float2(v.x - __bfloat162float(h2.x), v.y - __bfloat162float(h2.y)));
    __nv_bfloat16* o = P3 + r * 2304;
    *reinterpret_cast<__nv_bfloat162*>(o + c)        = h2;
    *reinterpret_cast<__nv_bfloat162*>(o + c + 768)  = h2;
    *reinterpret_cast<__nv_bfloat162*>(o + c + 1536) = l2;
    *reinterpret_cast<__half2*>(Ph + e) = __float22half2_rn(v);
}

__global__ void splitG_k(const float* __restrict__ in, __nv_bfloat16* __restrict__ out,
                         long long total2)
{
    long long i = (long long)blockIdx.x * blockDim.x + threadIdx.x;
    if (i >= total2) return;
    long long e = i * 2;
    float2 v = *reinterpret_cast<const float2*>(in + e);
    __nv_bfloat162 h2 = __float22bfloat162_rn(v);
    __nv_bfloat162 l2 = __float22bfloat162_rn(
        make_float2(v.x - __bfloat162float(h2.x), v.y - __bfloat162float(h2.y)));
    *reinterpret_cast<__nv_bfloat162*>(out + e)                   = h2;
    *reinterpret_cast<__nv_bfloat162*>(out + e + 768LL * 768)     = l2;
    *reinterpret_cast<__nv_bfloat162*>(out + e + 2LL * 768 * 768) = h2;
}

__global__ void cast_h(const float* __restrict__ in, __half* __restrict__ out, long long total2)
{
    long long i = (long long)blockIdx.x * blockDim.x + threadIdx.x;
    if (i >= total2) return;
    float2 v = *reinterpret_cast<const float2*>(in + i * 2);
    *reinterpret_cast<__half2*>(out + i * 2) = __float22half2_rn(v);
}

// ================= softmax over 1024 columns -> fp16 ==========
__global__ __launch_bounds__(256)
void softmax1024(const float* __restrict__ W, __half* __restrict__ Wh)
{
    const long long row = blockIdx.x;
    const float* w = W + row * 1024;
    const int t = threadIdx.x;
    float4 v = reinterpret_cast<const float4*>(w)[t];
    float m = fmaxf(fmaxf(v.x, v.y), fmaxf(v.z, v.w));
#pragma unroll
    for (int o = 16; o > 0; o >>= 1) m = fmaxf(m, __shfl_xor_sync(0xffffffffu, m, o));
    __shared__ float smax[8], ssum[8];
    if ((t & 31) == 0) smax[t >> 5] = m;
    __syncthreads();
    float bmax = smax[0];
#pragma unroll
    for (int i = 1; i < 8; i++) bmax = fmaxf(bmax, smax[i]);
    v.x = __expf(v.x - bmax); v.y = __expf(v.y - bmax);
    v.z = __expf(v.z - bmax); v.w = __expf(v.w - bmax);
    float s = v.x + v.y + v.z + v.w;
#pragma unroll
    for (int o = 16; o > 0; o >>= 1) s += __shfl_xor_sync(0xffffffffu, s, o);
    if ((t & 31) == 0) ssum[t >> 5] = s;
    __syncthreads();
    float tot = 0.f;
#pragma unroll
    for (int i = 0; i < 8; i++) tot += ssum[i];
    const float inv = 1.f / tot;
    __half* wh = Wh + row * 1024 + t * 4;
    *reinterpret_cast<__half2*>(wh)     = __float22half2_rn(make_float2(v.x * inv, v.y * inv));
    *reinterpret_cast<__half2*>(wh + 2) = __float22half2_rn(make_float2(v.z * inv, v.w * inv));
}

// ================= stream/event setup (static init, pre-checkpoint) ========
static cudaStream_t s2;
static cudaEvent_t ev_fork1, ev_join1, ev_fork2, ev_mp, ev_join2;
static struct StreamInit {
    StreamInit() {
        cudaStreamCreateWithFlags(&s2, cudaStreamNonBlocking);
        cudaEventCreateWithFlags(&ev_fork1, cudaEventDisableTiming);
        cudaEventCreateWithFlags(&ev_join1, cudaEventDisableTiming);
        cudaEventCreateWithFlags(&ev_fork2, cudaEventDisableTiming);
        cudaEventCreateWithFlags(&ev_mp, cudaEventDisableTiming);
        cudaEventCreateWithFlags(&ev_join2, cudaEventDisableTiming);
    }
} s_streamInit;

// ================= launch =================
static inline int blk2(long long total2) { return (int)((total2 + 255) / 256); }

extern "C" void kernel_launch(void* const* d_in, const int* in_sizes, int n_in,
                              void* d_out, int out_size)
{
    (void)in_sizes; (void)n_in; (void)out_size;
    const float* A     = (const float*)d_in[0];
    const float* P     = (const float*)d_in[1];
    const float* G_w   = (const float*)d_in[2];
    const float* G_b   = (const float*)d_in[3];
    const float* fca_w = (const float*)d_in[4];
    const float* fca_b = (const float*)d_in[5];
    const float* fcp_w = (const float*)d_in[6];
    const float* fcp_b = (const float*)d_in[7];
    float* out = (float*)d_out;

    float *W;
    cudaGetSymbolAddress((void**)&W,  g_W);
    __nv_bfloat16 *A3, *P3, *Ag3, *Gw3;
    cudaGetSymbolAddress((void**)&A3,  g_A3);
    cudaGetSymbolAddress((void**)&P3,  g_P3);
    cudaGetSymbolAddress((void**)&Ag3, g_Ag3);
    cudaGetSymbolAddress((void**)&Gw3, g_Gw3);
    __half *Wh, *Ph, *Agh, *U6h, *U7h, *Fah2, *Fph2;
    cudaGetSymbolAddress((void**)&Wh,   g_Wh);
    cudaGetSymbolAddress((void**)&Ph,   g_Ph);
    cudaGetSymbolAddress((void**)&Agh,  g_Agh);
    cudaGetSymbolAddress((void**)&U6h,  g_U6h);
    cudaGetSymbolAddress((void**)&U7h,  g_U7h);
    cudaGetSymbolAddress((void**)&Fah2, g_Fah2);
    cudaGetSymbolAddress((void**)&Fph2, g_Fph2);

    cudaFuncSetAttribute((const void*)tgemm<4,false,false,true>,  cudaFuncAttributeMaxDynamicSharedMemorySize, SMEMSZ);
    cudaFuncSetAttribute((const void*)tgemm<0,false,false,false>, cudaFuncAttributeMaxDynamicSharedMemorySize, SMEMSZ);
    cudaFuncSetAttribute((const void*)tgemm<3,true,false,true>,   cudaFuncAttributeMaxDynamicSharedMemorySize, SMEMSZ);
    cudaFuncSetAttribute((const void*)tgemm<3,true,true,true>,    cudaFuncAttributeMaxDynamicSharedMemorySize, SMEMSZ);
    cudaFuncSetAttribute((const void*)tgemm<2,true,false,true>,   cudaFuncAttributeMaxDynamicSharedMemorySize, SMEMSZ);

    // ---- fork 1: P/weight conversions on s2; A/G conversions + GEMM1 on main ----
    cudaEventRecord(ev_fork1, 0);
    cudaStreamWaitEvent(s2, ev_fork1, 0);

    splitP_k<<<blk2(32768LL*768/2), 256, 0, s2>>>(P, P3, Ph, 32768LL*768/2);
    cast_h<<<blk2(1536LL*768/2), 256, 0, s2>>>(fca_w, Fah2, 1536LL*768/2);
    cast_h<<<blk2(1536LL*768/2), 256, 0, s2>>>(fcp_w, Fph2, 1536LL*768/2);
    cudaEventRecord(ev_join1, s2);

    split3_k<<<blk2(16384LL*768/2), 256>>>(A, A3, 16384LL*768/2);
    splitG_k<<<blk2(768LL*768/2),   256>>>(G_w, Gw3, 768LL*768/2);

    // 1) Ag = A @ G_w + G_b  (bf16 triple-K; B-trans) -> Ag3 + Agh
    tgemm<4,false,false,true><<<dim3(6, 128, 1), 128, SMEMSZ>>>(
        (const uint16_t*)A3, (const uint16_t*)Gw3, G_b, nullptr, nullptr, Ag3, Agh,
        768, 2304, 2304, 768, 0, 0, 0);

    cudaStreamWaitEvent(0, ev_join1, 0);

    // 2) W = P @ Ag^T (per batch, bf16 triple-K) — monolithic
    tgemm<0,false,false,false><<<dim3(8, 16, 16), 128, SMEMSZ>>>(
        (const uint16_t*)P3, (const uint16_t*)Ag3, nullptr, nullptr, W, nullptr, nullptr,
        1024, 2304, 2304, 2304, 2048LL*2304, 1024LL*2304, 2048LL*1024);

    // 3) softmax over a-dim -> fp16 Wh — monolithic
    softmax1024<<<BSZ * PLEN, 256>>>(W, Wh);

    // ---- fork 2: s2 runs MA -> SA -> SP_part2; main runs MP -> SP_part1 ----
    cudaEventRecord(ev_fork2, 0);
    cudaStreamWaitEvent(s2, ev_fork2, 0);

    // 5) MA = W^T @ P (fp16; A-trans Wh, B-trans Ph), combo with Agh -> U6h (s2)
    tgemm<3,true,true,true><<<dim3(6, 8, 16), 128, SMEMSZ, s2>>>(
        (const uint16_t*)Wh, (const uint16_t*)Ph, nullptr, Agh, nullptr, U6h, nullptr,
        768, 2048, 1024, 768, 2048LL*1024, 2048LL*768, 1024LL*768);
    // 6) SA = relu(U6 @ fca_w + fca_b)  (s2)
    tgemm<2,true,false,true><<<dim3(6, 128, 1), 128, SMEMSZ, s2>>>(
        (const uint16_t*)U6h, (const uint16_t*)Fah2, fca_b, nullptr, out, nullptr, nullptr,
        768, 1536, 1536, 768, 0, 0, 0);

    // 4) MP = W @ Ag (fp16; B-trans Agh), combo with Ph -> U7h (main)
    tgemm<3,true,false,true><<<dim3(6, 16, 16), 128, SMEMSZ>>>(
        (const uint16_t*)Wh, (const uint16_t*)Agh, nullptr, Ph, nullptr, U7h, nullptr,
        768, 1024, 1024, 768, 2048LL*1024, 1024LL*768, 2048LL*768);
    cudaEventRecord(ev_mp, 0);

    // 7a) SP rows [0, 24576) on main (192 of 256 M-tiles)
    tgemm<2,true,false,true><<<dim3(6, 192, 1), 128, SMEMSZ>>>(
        (const uint16_t*)U7h, (const uint16_t*)Fph2, fcp_b, nullptr,
        out + 16384LL * 768, nullptr, nullptr,
        768, 1536, 1536, 768, 0, 0, 0);

    // 7b) SP rows [24576, 32768) on s2 (64 M-tiles), after SA and MP
    cudaStreamWaitEvent(s2, ev_mp, 0);
    tgemm<2,true,false,true><<<dim3(6, 64, 1), 128, SMEMSZ, s2>>>(
        (const uint16_t*)(U7h + 24576LL * 1536), (const uint16_t*)Fph2, fcp_b, nullptr,
        out + 16384LL * 768 + 24576LL * 768, nullptr, nullptr,
        768, 1536, 1536, 768, 0, 0, 0);
    cudaEventRecord(ev_join2, s2);

    cudaStreamWaitEvent(0, ev_join2, 0);
}

// round 14
// speedup vs baseline: 1.0379x; 1.0127x over previous
#include <cuda_runtime.h>
#include <cuda_bf16.h>
#include <cuda_fp16.h>
#include <cstdint>

// ---------------- problem constants ----------------
#define BSZ   16
#define ALEN 1024
#define PLEN 2048
#define LDIM 768

// ================= scratch (device globals) =================
__device__ __align__(256) float g_W [(size_t)BSZ * PLEN * ALEN];

// bf16 triple-K operand buffers (logit chain only)
__device__ __align__(256) __nv_bfloat16 g_A3 [(size_t)16384 * 2304];
__device__ __align__(256) __nv_bfloat16 g_P3 [(size_t)32768 * 2304];
__device__ __align__(256) __nv_bfloat16 g_Ag3[(size_t)16384 * 2304];
__device__ __align__(256) __nv_bfloat16 g_Gw3[(size_t)2304 * 768];   // [Kp,N] for B-trans

// fp16 single operand buffers (post-softmax chain) — all row-major
__device__ __align__(256) __half g_Wh  [(size_t)32768 * 1024];
__device__ __align__(256) __half g_Ph  [(size_t)32768 * 768];
__device__ __align__(256) __half g_Agh [(size_t)16384 * 768];
__device__ __align__(256) __half g_U6h [(size_t)16384 * 1536];
__device__ __align__(256) __half g_U7h [(size_t)32768 * 1536];
__device__ __align__(256) __half g_Fah2[(size_t)1536 * 768];
__device__ __align__(256) __half g_Fph2[(size_t)1536 * 768];

// ================= helpers =================
__device__ __forceinline__ uint32_t smem_u32(const void* p) {
    uint32_t a;
    asm("{ .reg .u64 t; cvta.to.shared.u64 t, %1; cvt.u32.u64 %0, t; }" : "=r"(a) : "l"(p));
    return a;
}

#define LDSM4(r0, r1, r2, r3, a)                                              \
    asm volatile("ldmatrix.sync.aligned.m8n8.x4.shared.b16 {%0,%1,%2,%3}, [%4];" \
                 : "=r"(r0), "=r"(r1), "=r"(r2), "=r"(r3) : "r"(a))
#define LDSM4T(r0, r1, r2, r3, a)                                             \
    asm volatile("ldmatrix.sync.aligned.m8n8.x4.trans.shared.b16 {%0,%1,%2,%3}, [%4];" \
                 : "=r"(r0), "=r"(r1), "=r"(r2), "=r"(r3) : "r"(a))

__device__ __forceinline__ void mma_bf16(float* c, uint32_t a0, uint32_t a1, uint32_t a2,
                                         uint32_t a3, uint32_t b0, uint32_t b1) {
    asm volatile("mma.sync.aligned.m16n8k16.row.col.f32.bf16.bf16.f32 "
                 "{%0,%1,%2,%3}, {%4,%5,%6,%7}, {%8,%9}, {%0,%1,%2,%3};"
                 : "+f"(c[0]), "+f"(c[1]), "+f"(c[2]), "+f"(c[3])
                 : "r"(a0), "r"(a1), "r"(a2), "r"(a3), "r"(b0), "r"(b1));
}
__device__ __forceinline__ void mma_fp16(float* c, uint32_t a0, uint32_t a1, uint32_t a2,
                                         uint32_t a3, uint32_t b0, uint32_t b1) {
    asm volatile("mma.sync.aligned.m16n8k16.row.col.f32.f16.f16.f32 "
                 "{%0,%1,%2,%3}, {%4,%5,%6,%7}, {%8,%9}, {%0,%1,%2,%3};"
                 : "+f"(c[0]), "+f"(c[1]), "+f"(c[2]), "+f"(c[3])
                 : "r"(a0), "r"(a1), "r"(a2), "r"(a3), "r"(b0), "r"(b1));
}

// ================= tensor-core GEMM (mma.sync) =================
// C[M,N](f32) = opA(A) * opB(B)^T-style, 16-bit operands.
// 128x128 block tile, 128 threads (2x2 warps, 64x64 warp tile),
// K-chunk 64, 3-stage cp.async pipeline, 2 CTAs/SM, fragment double-buffer.
// TA/TB: operand stored [Kp, M/N] row-major, consumed via ldmatrix.trans.
// EPI: 0 fp32 C | 1 +bias | 2 relu(+bias)
//      3 combo: fp16 out2[r,c]=C-aux, out2[r,c+N]=C*aux (aux fp16, stride 2N)
//      4 Ag: bias add; bf16 triple out2 (hi,lo,hi; stride 3N) + fp16 out3
#define NSTRIDE 144
#define TSTRIDE 272
#define TILEB   18432
#define STAGEB  (2 * TILEB)
#define NSTAGE  3
#define SMEMSZ  (NSTAGE * STAGEB)   // 110592 B

__device__ __forceinline__ void ld_tile_n(uint32_t sdst, const char* g, int rowB, int tid) {
#pragma unroll
    for (int i = 0; i < 8; i++) {
        int idx = i * 128 + tid;
        int row = idx >> 3;
        int c = idx & 7;
        asm volatile("cp.async.cg.shared.global [%0], [%1], 16;\n"
                     :: "r"(sdst + row * NSTRIDE + c * 16),
                        "l"(g + (long long)row * rowB + c * 16));
    }
}
__device__ __forceinline__ void ld_tile_t(uint32_t sdst, const char* g, int rowB, int tid) {
#pragma unroll
    for (int i = 0; i < 8; i++) {
        int idx = i * 128 + tid;
        int row = idx >> 4;
        int c = idx & 15;
        asm volatile("cp.async.cg.shared.global [%0], [%1], 16;\n"
                     :: "r"(sdst + row * TSTRIDE + c * 16),
                        "l"(g + (long long)row * rowB + c * 16));
    }
}

template<int EPI, bool FP16, bool TA, bool TB>
__global__ __launch_bounds__(128, 2)
void tgemm(const uint16_t* __restrict__ Aop,
           const uint16_t* __restrict__ Bop,
           const float* __restrict__ bias,
           const __half* __restrict__ aux,
           float* __restrict__ Cout,
           void* __restrict__ out2,
           void* __restrict__ out3,
           int N, int Kp, int ldA, int ldB,
           long long bsA, long long bsB, long long bsC)
{
    extern __shared__ __align__(128) char smem[];
    const uint32_t sbase = smem_u32(smem);
    const int tid  = threadIdx.x;
    const int wid  = tid >> 5;
    const int lane = tid & 31;
    const int wm = wid & 1;
    const int wn = wid >> 1;

    const int rowBA = ldA * 2;
    const int rowBB = ldB * 2;
    const char* Abase = ((const char*)Aop) + 2LL * (bsA * blockIdx.z +
                        (TA ? (long long)blockIdx.y * 128
                            : (long long)blockIdx.y * 128 * ldA));
    const char* Bbase = ((const char*)Bop) + 2LL * (bsB * blockIdx.z +
                        (TB ? (long long)blockIdx.x * 128
                            : (long long)blockIdx.x * 128 * ldB));

    const int ntiles = Kp >> 6;

    float c[4][8][4];
#pragma unroll
    for (int i = 0; i < 4; i++)
#pragma unroll
        for (int j = 0; j < 8; j++) {
            c[i][j][0] = 0.f; c[i][j][1] = 0.f; c[i][j][2] = 0.f; c[i][j][3] = 0.f;
        }

    auto a_chunk = [&](int k) -> const char* {
        return TA ? Abase + (long long)k * 64 * rowBA : Abase + k * 128;
    };
    auto b_chunk = [&](int k) -> const char* {
        return TB ? Bbase + (long long)k * 64 * rowBB : Bbase + k * 128;
    };

#pragma unroll
    for (int s = 0; s < 2; s++) {
        if (TA) ld_tile_t(sbase + s * STAGEB,         a_chunk(s), rowBA, tid);
        else    ld_tile_n(sbase + s * STAGEB,         a_chunk(s), rowBA, tid);
        if (TB) ld_tile_t(sbase + s * STAGEB + TILEB, b_chunk(s), rowBB, tid);
        else    ld_tile_n(sbase + s * STAGEB + TILEB, b_chunk(s), rowBB, tid);
        asm volatile("cp.async.commit_group;\n" ::: "memory");
    }

    const uint32_t aoff = TA
        ? (uint32_t)(((lane & 7) + ((lane >> 4) << 3)) * TSTRIDE + (((lane >> 3) & 1) << 4)
                     + wm * 128)
        : (uint32_t)((wm * 64 + (lane & 15)) * NSTRIDE + ((lane >> 4) << 4));
    const uint32_t boff = TB
        ? (uint32_t)((lane & 15) * TSTRIDE + ((lane >> 4) << 4) + wn * 128)
        : (uint32_t)((wn * 64 + ((lane >> 4) << 3) + (lane & 7)) * NSTRIDE
                     + (((lane >> 3) & 1) << 4));

    uint32_t afb[2][16], bfb[2][16];

    for (int ks = 0; ks < ntiles; ks++) {
        const int b = ks % NSTAGE;
        asm volatile("cp.async.wait_group 1;\n" ::: "memory");
        __syncthreads();

        const uint32_t sA = sbase + b * STAGEB;
        const uint32_t sB = sA + TILEB;

#pragma unroll
        for (int bi = 0; bi < 4; bi++) {
            if (TB) LDSM4T(bfb[0][bi*4+0], bfb[0][bi*4+1], bfb[0][bi*4+2], bfb[0][bi*4+3],
                           sB + boff + bi * 32);
            else    LDSM4 (bfb[0][bi*4+0], bfb[0][bi*4+1], bfb[0][bi*4+2], bfb[0][bi*4+3],
                           sB + boff + bi * 16 * NSTRIDE);
        }
#pragma unroll
        for (int mt = 0; mt < 4; mt++) {
            if (TA) LDSM4T(afb[0][mt*4+0], afb[0][mt*4+1], afb[0][mt*4+2], afb[0][mt*4+3],
                           sA + aoff + mt * 32);
            else    LDSM4 (afb[0][mt*4+0], afb[0][mt*4+1], afb[0][mt*4+2], afb[0][mt*4+3],
                           sA + aoff + mt * 16 * NSTRIDE);
        }

#pragma unroll
        for (int kk = 0; kk < 4; kk++) {
            const int cur = kk & 1;
            const int nxt = cur ^ 1;
            if (kk < 3) {
#pragma unroll
                for (int bi = 0; bi < 4; bi++) {
                    if (TB) LDSM4T(bfb[nxt][bi*4+0], bfb[nxt][bi*4+1], bfb[nxt][bi*4+2], bfb[nxt][bi*4+3],
                                   sB + boff + (kk + 1) * 16 * TSTRIDE + bi * 32);
                    else    LDSM4 (bfb[nxt][bi*4+0], bfb[nxt][bi*4+1], bfb[nxt][bi*4+2], bfb[nxt][bi*4+3],
                                   sB + boff + bi * 16 * NSTRIDE + (kk + 1) * 32);
                }
#pragma unroll
                for (int mt = 0; mt < 4; mt++) {
                    if (TA) LDSM4T(afb[nxt][mt*4+0], afb[nxt][mt*4+1], afb[nxt][mt*4+2], afb[nxt][mt*4+3],
                                   sA + aoff + (kk + 1) * 16 * TSTRIDE + mt * 32);
                    else    LDSM4 (afb[nxt][mt*4+0], afb[nxt][mt*4+1], afb[nxt][mt*4+2], afb[nxt][mt*4+3],
                                   sA + aoff + mt * 16 * NSTRIDE + (kk + 1) * 32);
                }
            }
#pragma unroll
            for (int mt = 0; mt < 4; mt++) {
#pragma unroll
                for (int bi = 0; bi < 4; bi++) {
                    if (FP16) {
                        mma_fp16(c[mt][2*bi],   afb[cur][mt*4+0], afb[cur][mt*4+1],
                                 afb[cur][mt*4+2], afb[cur][mt*4+3],
                                 bfb[cur][bi*4+0], bfb[cur][bi*4+1]);
                        mma_fp16(c[mt][2*bi+1], afb[cur][mt*4+0], afb[cur][mt*4+1],
                                 afb[cur][mt*4+2], afb[cur][mt*4+3],
                                 bfb[cur][bi*4+2], bfb[cur][bi*4+3]);
                    } else {
                        mma_bf16(c[mt][2*bi],   afb[cur][mt*4+0], afb[cur][mt*4+1],
                                 afb[cur][mt*4+2], afb[cur][mt*4+3],
                                 bfb[cur][bi*4+0], bfb[cur][bi*4+1]);
                        mma_bf16(c[mt][2*bi+1], afb[cur][mt*4+0], afb[cur][mt*4+1],
                                 afb[cur][mt*4+2], afb[cur][mt*4+3],
                                 bfb[cur][bi*4+2], bfb[cur][bi*4+3]);
                    }
                }
            }
        }

        const int kl = ks + 2;
        if (kl < ntiles) {
            const int bl = kl % NSTAGE;
            if (TA) ld_tile_t(sbase + bl * STAGEB,         a_chunk(kl), rowBA, tid);
            else    ld_tile_n(sbase + bl * STAGEB,         a_chunk(kl), rowBA, tid);
            if (TB) ld_tile_t(sbase + bl * STAGEB + TILEB, b_chunk(kl), rowBB, tid);
            else    ld_tile_n(sbase + bl * STAGEB + TILEB, b_chunk(kl), rowBB, tid);
        }
        asm volatile("cp.async.commit_group;\n" ::: "memory");
    }

    // ---- epilogue ----
    const long long bz = blockIdx.z;
    const int row0 = blockIdx.y * 128 + wm * 64 + (lane >> 2);
    const int col0 = blockIdx.x * 128 + wn * 64 + (lane & 3) * 2;

#pragma unroll
    for (int mt = 0; mt < 4; mt++) {
#pragma unroll
        for (int nt = 0; nt < 8; nt++) {
            const int r = row0 + mt * 16;
            const int cl = col0 + nt * 8;
            float2 v0 = make_float2(c[mt][nt][0], c[mt][nt][1]);
            float2 v1 = make_float2(c[mt][nt][2], c[mt][nt][3]);

            if (EPI == 3) {
                const __half* Yb = aux + bsC * bz;
                __half* Ub = ((__half*)out2) + 2 * bsC * bz;
                const int ustr = 2 * N;
                float2 y0 = __half22float2(
                    *reinterpret_cast<const __half2*>(Yb + (long long)r * N + cl));
                float2 y1 = __half22float2(
                    *reinterpret_cast<const __half2*>(Yb + (long long)(r + 8) * N + cl));
                *reinterpret_cast<__half2*>(Ub + (long long)r * ustr + cl) =
                    __float22half2_rn(make_float2(v0.x - y0.x, v0.y - y0.y));
                *reinterpret_cast<__half2*>(Ub + (long long)r * ustr + cl + N) =
                    __float22half2_rn(make_float2(v0.x * y0.x, v0.y * y0.y));
                *reinterpret_cast<__half2*>(Ub + (long long)(r + 8) * ustr + cl) =
                    __float22half2_rn(make_float2(v1.x - y1.x, v1.y - y1.y));
                *reinterpret_cast<__half2*>(Ub + (long long)(r + 8) * ustr + cl + N) =
                    __float22half2_rn(make_float2(v1.x * y1.x, v1.y * y1.y));
                continue;
            }

            if (EPI == 1 || EPI == 2 || EPI == 4) {
                float2 bv = *reinterpret_cast<const float2*>(bias + cl);
                v0.x += bv.x; v0.y += bv.y; v1.x += bv.x; v1.y += bv.y;
            }
            if (EPI == 2) {
                v0.x = fmaxf(v0.x, 0.f); v0.y = fmaxf(v0.y, 0.f);
                v1.x = fmaxf(v1.x, 0.f); v1.y = fmaxf(v1.y, 0.f);
            }
            if (EPI <= 2) {
                float* Cb = Cout + bsC * bz;
                *reinterpret_cast<float2*>(Cb + (long long)r * N + cl)       = v0;
                *reinterpret_cast<float2*>(Cb + (long long)(r + 8) * N + cl) = v1;
            }

            if (EPI == 4) {
                __nv_bfloat16* T = (__nv_bfloat16*)out2;
                const int tstr = 3 * N;
                __nv_bfloat162 h0 = __float22bfloat162_rn(v0);
                __nv_bfloat162 h1 = __float22bfloat162_rn(v1);
                __nv_bfloat162 l0 = __float22bfloat162_rn(
                    make_float2(v0.x - __bfloat162float(h0.x), v0.y - __bfloat162float(h0.y)));
                __nv_bfloat162 l1 = __float22bfloat162_rn(
                    make_float2(v1.x - __bfloat162float(h1.x), v1.y - __bfloat162float(h1.y)));
                *reinterpret_cast<__nv_bfloat162*>(T + (long long)r * tstr + cl)          = h0;
                *reinterpret_cast<__nv_bfloat162*>(T + (long long)r * tstr + cl + N)      = l0;
                *reinterpret_cast<__nv_bfloat162*>(T + (long long)r * tstr + cl + 2 * N)  = h0;
                *reinterpret_cast<__nv_bfloat162*>(T + (long long)(r + 8) * tstr + cl)         = h1;
                *reinterpret_cast<__nv_bfloat162*>(T + (long long)(r + 8) * tstr + cl + N)     = l1;
                *reinterpret_cast<__nv_bfloat162*>(T + (long long)(r + 8) * tstr + cl + 2 * N) = h1;
                __half* Ah = (__half*)out3;
                *reinterpret_cast<__half2*>(Ah + (long long)r * N + cl)       = __float22half2_rn(v0);
                *reinterpret_cast<__half2*>(Ah + (long long)(r + 8) * N + cl) = __float22half2_rn(v1);
            }
        }
    }
}

// ================= conversion kernels (all pure streaming) =================
__global__ void split3_k(const float* __restrict__ in, __nv_bfloat16* __restrict__ out,
                         long long total2)
{
    long long i = (long long)blockIdx.x * blockDim.x + threadIdx.x;
    if (i >= total2) return;
    long long e = i * 2;
    long long r = e / 768;
    int c = (int)(e - r * 768);
    float2 v = *reinterpret_cast<const float2*>(in + e);
    __nv_bfloat162 h2 = __float22bfloat162_rn(v);
    __nv_bfloat162 l2 = __float22bfloat162_rn(
        make_float2(v.x - __bfloat162float(h2.x), v.y - __bfloat162float(h2.y)));
    __nv_bfloat16* o = out + r * 2304;
    *reinterpret_cast<__nv_bfloat162*>(o + c)        = h2;
    *reinterpret_cast<__nv_bfloat162*>(o + c + 768)  = h2;
    *reinterpret_cast<__nv_bfloat162*>(o + c + 1536) = l2;
}

__global__ void splitP_k(const float* __restrict__ in, __nv_bfloat16* __restrict__ P3,
                         __half* __restrict__ Ph, long long total2)
{
    long long i = (long long)blockIdx.x * blockDim.x + threadIdx.x;
    if (i >= total2) return;
    long long e = i * 2;
    long long r = e / 768;
    int c = (int)(e - r * 768);
    float2 v = *reinterpret_cast<const float2*>(in + e);
    __nv_bfloat162 h2 = __float22bfloat162_rn(v);
    __nv_bfloat162 l2 = __float22bfloat162_rn(
        make_float2(v.x - __bfloat162float(h2.x), v.y - __bfloat162float(h2.y)));
    __nv_bfloat16* o = P3 + r * 2304;
    *reinterpret_cast<__nv_bfloat162*>(o + c)        = h2;
    *reinterpret_cast<__nv_bfloat162*>(o + c + 768)  = h2;
    *reinterpret_cast<__nv_bfloat162*>(o + c + 1536) = l2;
    *reinterpret_cast<__half2*>(Ph + e) = __float22half2_rn(v);
}

__global__ void splitG_k(const float* __restrict__ in, __nv_bfloat16* __restrict__ out,
                         long long total2)
{
    long long i = (long long)blockIdx.x * blockDim.x + threadIdx.x;
    if (i >= total2) return;
    long long e = i * 2;
    float2 v = *reinterpret_cast<const float2*>(in + e);
    __nv_bfloat162 h2 = __float22bfloat162_rn(v);
    __nv_bfloat162 l2 = __float22bfloat162_rn(
        make_float2(v.x - __bfloat162float(h2.x), v.y - __bfloat162float(h2.y)));
    *reinterpret_cast<__nv_bfloat162*>(out + e)                   = h2;
    *reinterpret_cast<__nv_bfloat162*>(out + e + 768LL * 768)     = l2;
    *reinterpret_cast<__nv_bfloat162*>(out + e + 2LL * 768 * 768) = h2;
}

__global__ void cast_h(const float* __restrict__ in, __half* __restrict__ out, long long total2)
{
    long long i = (long long)blockIdx.x * blockDim.x + threadIdx.x;
    if (i >= total2) return;
    float2 v = *reinterpret_cast<const float2*>(in + i * 2);
    *reinterpret_cast<__half2*>(out + i * 2) = __float22half2_rn(v);
}

// ================= softmax over 1024 columns -> fp16 ==========
__global__ __launch_bounds__(256)
void softmax1024(const float* __restrict__ W, __half* __restrict__ Wh)
{
    const long long row = blockIdx.x;
    const float* w = W + row * 1024;
    const int t = threadIdx.x;
    float4 v = reinterpret_cast<const float4*>(w)[t];
    float m = fmaxf(fmaxf(v.x, v.y), fmaxf(v.z, v.w));
#pragma unroll
    for (int o = 16; o > 0; o >>= 1) m = fmaxf(m, __shfl_xor_sync(0xffffffffu, m, o));
    __shared__ float smax[8], ssum[8];
    if ((t & 31) == 0) smax[t >> 5] = m;
    __syncthreads();
    float bmax = smax[0];
#pragma unroll
    for (int i = 1; i < 8; i++) bmax = fmaxf(bmax, smax[i]);
    v.x = __expf(v.x - bmax); v.y = __expf(v.y - bmax);
    v.z = __expf(v.z - bmax); v.w = __expf(v.w - bmax);
    float s = v.x + v.y + v.z + v.w;
#pragma unroll
    for (int o = 16; o > 0; o >>= 1) s += __shfl_xor_sync(0xffffffffu, s, o);
    if ((t & 31) == 0) ssum[t >> 5] = s;
    __syncthreads();
    float tot = 0.f;
#pragma unroll
    for (int i = 0; i < 8; i++) tot += ssum[i];
    const float inv = 1.f / tot;
    __half* wh = Wh + row * 1024 + t * 4;
    *reinterpret_cast<__half2*>(wh)     = __float22half2_rn(make_float2(v.x * inv, v.y * inv));
    *reinterpret_cast<__half2*>(wh + 2) = __float22half2_rn(make_float2(v.z * inv, v.w * inv));
}

// ================= stream/event setup (static init, pre-checkpoint) ========
static cudaStream_t s2;
static cudaEvent_t ev_fork1, ev_join1, ev_g0, ev_g1, ev_sm, ev_join2;
static struct StreamInit {
    StreamInit() {
        cudaStreamCreateWithFlags(&s2, cudaStreamNonBlocking);
        cudaEventCreateWithFlags(&ev_fork1, cudaEventDisableTiming);
        cudaEventCreateWithFlags(&ev_join1, cudaEventDisableTiming);
        cudaEventCreateWithFlags(&ev_g0, cudaEventDisableTiming);
        cudaEventCreateWithFlags(&ev_g1, cudaEventDisableTiming);
        cudaEventCreateWithFlags(&ev_sm, cudaEventDisableTiming);
        cudaEventCreateWithFlags(&ev_join2, cudaEventDisableTiming);
    }
} s_streamInit;

// ================= launch =================
static inline int blk2(long long total2) { return (int)((total2 + 255) / 256); }

extern "C" void kernel_launch(void* const* d_in, const int* in_sizes, int n_in,
                              void* d_out, int out_size)
{
    (void)in_sizes; (void)n_in; (void)out_size;
    const float* A     = (const float*)d_in[0];
    const float* P     = (const float*)d_in[1];
    const float* G_w   = (const float*)d_in[2];
    const float* G_b   = (const float*)d_in[3];
    const float* fca_w = (const float*)d_in[4];
    const float* fca_b = (const float*)d_in[5];
    const float* fcp_w = (const float*)d_in[6];
    const float* fcp_b = (const float*)d_in[7];
    float* out = (float*)d_out;

    float *W;
    cudaGetSymbolAddress((void**)&W,  g_W);
    __nv_bfloat16 *A3, *P3, *Ag3, *Gw3;
    cudaGetSymbolAddress((void**)&A3,  g_A3);
    cudaGetSymbolAddress((void**)&P3,  g_P3);
    cudaGetSymbolAddress((void**)&Ag3, g_Ag3);
    cudaGetSymbolAddress((void**)&Gw3, g_Gw3);
    __half *Wh, *Ph, *Agh, *U6h, *U7h, *Fah2, *Fph2;
    cudaGetSymbolAddress((void**)&Wh,   g_Wh);
    cudaGetSymbolAddress((void**)&Ph,   g_Ph);
    cudaGetSymbolAddress((void**)&Agh,  g_Agh);
    cudaGetSymbolAddress((void**)&U6h,  g_U6h);
    cudaGetSymbolAddress((void**)&U7h,  g_U7h);
    cudaGetSymbolAddress((void**)&Fah2, g_Fah2);
    cudaGetSymbolAddress((void**)&Fph2, g_Fph2);

    cudaFuncSetAttribute((const void*)tgemm<4,false,false,true>,  cudaFuncAttributeMaxDynamicSharedMemorySize, SMEMSZ);
    cudaFuncSetAttribute((const void*)tgemm<0,false,false,false>, cudaFuncAttributeMaxDynamicSharedMemorySize, SMEMSZ);
    cudaFuncSetAttribute((const void*)tgemm<3,true,false,true>,   cudaFuncAttributeMaxDynamicSharedMemorySize, SMEMSZ);
    cudaFuncSetAttribute((const void*)tgemm<3,true,true,true>,    cudaFuncAttributeMaxDynamicSharedMemorySize, SMEMSZ);
    cudaFuncSetAttribute((const void*)tgemm<2,true,false,true>,   cudaFuncAttributeMaxDynamicSharedMemorySize, SMEMSZ);

    // ---- fork 1: P/weight conversions on s2; A/G conversions + GEMM1 on main ----
    cudaEventRecord(ev_fork1, 0);
    cudaStreamWaitEvent(s2, ev_fork1, 0);

    splitP_k<<<blk2(32768LL*768/2), 256, 0, s2>>>(P, P3, Ph, 32768LL*768/2);
    cast_h<<<blk2(1536LL*768/2), 256, 0, s2>>>(fca_w, Fah2, 1536LL*768/2);
    cast_h<<<blk2(1536LL*768/2), 256, 0, s2>>>(fcp_w, Fph2, 1536LL*768/2);
    cudaEventRecord(ev_join1, s2);

    split3_k<<<blk2(16384LL*768/2), 256>>>(A, A3, 16384LL*768/2);
    splitG_k<<<blk2(768LL*768/2),   256>>>(G_w, Gw3, 768LL*768/2);

    // 1) Ag = A @ G_w + G_b  (bf16 triple-K; B-trans) -> Ag3 + Agh
    tgemm<4,false,false,true><<<dim3(6, 128, 1), 128, SMEMSZ>>>(
        (const uint16_t*)A3, (const uint16_t*)Gw3, G_b, nullptr, nullptr, Ag3, Agh,
        768, 2304, 2304, 768, 0, 0, 0);

    cudaStreamWaitEvent(0, ev_join1, 0);

    // 2+3) GEMM2 in 2 half-batch groups; softmax of group 0 overlaps group 1
    //      (each group = 1024 CTAs ≈ 3.5 waves — no sub-wave fragmentation)
    tgemm<0,false,false,false><<<dim3(8, 16, 8), 128, SMEMSZ>>>(
        (const uint16_t*)P3, (const uint16_t*)Ag3, nullptr, nullptr, W, nullptr, nullptr,
        1024, 2304, 2304, 2304, 2048LL*2304, 1024LL*2304, 2048LL*1024);
    cudaEventRecord(ev_g0, 0);
    cudaStreamWaitEvent(s2, ev_g0, 0);
    softmax1024<<<8 * PLEN, 256, 0, s2>>>(W, Wh);

    tgemm<0,false,false,false><<<dim3(8, 16, 8), 128, SMEMSZ>>>(
        (const uint16_t*)(P3 + 8LL * 2048 * 2304),
        (const uint16_t*)(Ag3 + 8LL * 1024 * 2304),
        nullptr, nullptr, W + 8LL * 2048 * 1024, nullptr, nullptr,
        1024, 2304, 2304, 2304, 2048LL*2304, 1024LL*2304, 2048LL*1024);
    cudaEventRecord(ev_g1, 0);
    cudaStreamWaitEvent(s2, ev_g1, 0);
    softmax1024<<<8 * PLEN, 256, 0, s2>>>(W + 8LL * 2048 * 1024, Wh + 8LL * 2048 * 1024);
    cudaEventRecord(ev_sm, s2);

    // ---- tails (exact round-11): s2 runs MA -> SA; main runs MP -> SP ----
    // 5) MA = W^T @ P (fp16; A-trans Wh, B-trans Ph), combo with Agh -> U6h (s2)
    tgemm<3,true,true,true><<<dim3(6, 8, 16), 128, SMEMSZ, s2>>>(
        (const uint16_t*)Wh, (const uint16_t*)Ph, nullptr, Agh, nullptr, U6h, nullptr,
        768, 2048, 1024, 768, 2048LL*1024, 2048LL*768, 1024LL*768);
    // 6) SA = relu(U6 @ fca_w + fca_b)  (s2)
    tgemm<2,true,false,true><<<dim3(6, 128, 1), 128, SMEMSZ, s2>>>(
        (const uint16_t*)U6h, (const uint16_t*)Fah2, fca_b, nullptr, out, nullptr, nullptr,
        768, 1536, 1536, 768, 0, 0, 0);
    cudaEventRecord(ev_join2, s2);

    // 4) MP = W @ Ag (fp16; B-trans Agh), combo with Ph -> U7h (main)
    cudaStreamWaitEvent(0, ev_sm, 0);
    tgemm<3,true,false,true><<<dim3(6, 16, 16), 128, SMEMSZ>>>(
        (const uint16_t*)Wh, (const uint16_t*)Agh, nullptr, Ph, nullptr, U7h, nullptr,
        768, 1024, 1024, 768, 2048LL*1024, 1024LL*768, 2048LL*768);
    // 7) SP = relu(U7 @ fcp_w + fcp_b)  (main, monolithic)
    tgemm<2,true,false,true><<<dim3(6, 256, 1), 128, SMEMSZ>>>(
        (const uint16_t*)U7h, (const uint16_t*)Fph2, fcp_b, nullptr,
        out + 16384LL * 768, nullptr, nullptr,
        768, 1536, 1536, 768, 0, 0, 0);

    cudaStreamWaitEvent(0, ev_join2, 0);
}